// round 16
// baseline (speedup 1.0000x reference)
#include <cuda_runtime.h>
#include <cuda_fp16.h>
#include <cstdint>

#define MAX_T 1000000
#define MAX_N 50000

// ---- scratch (static __device__; no allocation anywhere) ----
__device__ __half g_x[(size_t)MAX_T * 128];   // pre-BN GEMM output (fp16, 256 MB)
__device__ float  g_aggr[MAX_N * 64];
__device__ float  g_bn1sum[64 * 128], g_bn1sq[64 * 128];
__device__ float  g_s1[128], g_sh1[128];
__device__ float  g_bn2sum[64], g_bn2sq[64];
__device__ float  g_s2[64], g_sh2[64];

static constexpr int RS = 216;                 // fp16 row stride (432 B: ldmatrix conflict-free)
static constexpr int A_TILE_H = 128 * RS;      // halves per A tile
static constexpr int SMEM_TOTAL = (3 * A_TILE_H) * 2 + 512;   // W + 2*A + bias = 166400 B

__device__ __forceinline__ uint32_t smem_u32(const void* p) {
    uint32_t a;
    asm("{ .reg .u64 t; cvta.to.shared.u64 t, %1; cvt.u32.u64 %0, t; }" : "=r"(a) : "l"(p));
    return a;
}
__device__ __forceinline__ void ldsm_x4(uint32_t& r0, uint32_t& r1, uint32_t& r2, uint32_t& r3,
                                        uint32_t addr) {
    asm volatile("ldmatrix.sync.aligned.m8n8.x4.shared.b16 {%0,%1,%2,%3}, [%4];"
                 : "=r"(r0), "=r"(r1), "=r"(r2), "=r"(r3) : "r"(addr));
}
__device__ __forceinline__ void stsm_x4(uint32_t addr, uint32_t r0, uint32_t r1,
                                        uint32_t r2, uint32_t r3) {
    asm volatile("stmatrix.sync.aligned.m8n8.x4.shared.b16 [%0], {%1,%2,%3,%4};"
                 :: "r"(addr), "r"(r0), "r"(r1), "r"(r2), "r"(r3) : "memory");
}
// fp16-accumulate HMMA
__device__ __forceinline__ void mma16816h(uint32_t* d, uint32_t a0, uint32_t a1, uint32_t a2,
                                          uint32_t a3, uint32_t b0, uint32_t b1) {
    asm volatile("mma.sync.aligned.m16n8k16.row.col.f16.f16.f16.f16 "
                 "{%0,%1}, {%2,%3,%4,%5}, {%6,%7}, {%0,%1};"
                 : "+r"(d[0]), "+r"(d[1])
                 : "r"(a0), "r"(a1), "r"(a2), "r"(a3), "r"(b0), "r"(b1));
}
__device__ __forceinline__ uint4 pack8(float4 a, float4 b) {
    __half2 h0 = __float22half2_rn(make_float2(a.x, a.y));
    __half2 h1 = __float22half2_rn(make_float2(a.z, a.w));
    __half2 h2 = __float22half2_rn(make_float2(b.x, b.y));
    __half2 h3 = __float22half2_rn(make_float2(b.z, b.w));
    uint4 u;
    u.x = *reinterpret_cast<uint32_t*>(&h0);
    u.y = *reinterpret_cast<uint32_t*>(&h1);
    u.z = *reinterpret_cast<uint32_t*>(&h2);
    u.w = *reinterpret_cast<uint32_t*>(&h3);
    return u;
}
__device__ __forceinline__ uint2 pack4(float4 a) {
    __half2 h0 = __float22half2_rn(make_float2(a.x, a.y));
    __half2 h1 = __float22half2_rn(make_float2(a.z, a.w));
    uint2 u;
    u.x = *reinterpret_cast<uint32_t*>(&h0);
    u.y = *reinterpret_cast<uint32_t*>(&h1);
    return u;
}

// Full (unpipelined) A-tile build — prologue tile only.
__device__ __forceinline__ void build_A(
    __half* abuf, int tile, int T, int E,
    const float* __restrict__ atom, const float* __restrict__ edge,
    const float* __restrict__ rij,  const float* __restrict__ dist,
    const int* __restrict__ eidx,   const int* __restrict__ trip, int tid)
{
    const int row = tid >> 2, q = tid & 3;
    int t = tile * 128 + row;
    if (t >= T) t = T - 1;
    const int e1 = trip[t], e2 = trip[T + t];
    __half* dst = abuf + row * RS;

    if (q == 3) {
        float ax = rij[3*e1], ay = rij[3*e1+1], az = rij[3*e1+2];
        float bx = rij[3*e2], by = rij[3*e2+1], bz = rij[3*e2+2];
        float d1 = fmaxf(dist[e1], 1e-8f), d2 = fmaxf(dist[e2], 1e-8f);
        float ca = (ax*bx + ay*by + az*bz) / (d1 * d2);
        ca = fminf(1.0f, fmaxf(-1.0f, ca));
        #pragma unroll
        for (int g = 0; g < 2; ++g) {
            __half2 hh[4];
            #pragma unroll
            for (int j = 0; j < 4; ++j) {
                int k0 = g * 8 + 2 * j;
                float u0 = ca - (-1.0f + 0.13333333333333333f * (float)k0);
                float u1 = ca - (-1.0f + 0.13333333333333333f * (float)(k0 + 1));
                hh[j] = __float22half2_rn(make_float2(
                    __expf(-u0 * u0 * 44.444444444444444f),
                    __expf(-u1 * u1 * 44.444444444444444f)));
            }
            uint4 u;
            u.x = *reinterpret_cast<uint32_t*>(&hh[0]);
            u.y = *reinterpret_cast<uint32_t*>(&hh[1]);
            u.z = *reinterpret_cast<uint32_t*>(&hh[2]);
            u.w = *reinterpret_cast<uint32_t*>(&hh[3]);
            reinterpret_cast<uint4*>(dst + 192)[g] = u;
        }
    } else {
        const float* base = (q == 0) ? atom + (size_t)eidx[E + e1] * 64
                          : (q == 1) ? edge + (size_t)e1 * 64
                                     : edge + (size_t)e2 * 64;
        const float4* src = reinterpret_cast<const float4*>(base);
        uint4* d4 = reinterpret_cast<uint4*>(dst + q * 64);
        #pragma unroll
        for (int u = 0; u < 8; ++u) d4[u] = pack8(src[2*u], src[2*u + 1]);
    }
}

// ==== kernel A: HMMA gather-GEMM, coalesced gather, stmatrix epilogue (R13 form) ====
__global__ void __launch_bounds__(512, 1) kA(
    const float* __restrict__ atom, const float* __restrict__ edge,
    const float* __restrict__ rij,  const float* __restrict__ dist,
    const float* __restrict__ fcw,  const float* __restrict__ fcb,
    const int*   __restrict__ eidx, const int*   __restrict__ trip,
    int T, int E)
{
    extern __shared__ __half sm[];
    __half* sW  = sm;                       // [128 ch][RS]
    __half* sA0 = sm + A_TILE_H;
    __half* sA1 = sm + 2 * A_TILE_H;
    float*  sBias = reinterpret_cast<float*>(sm + 3 * A_TILE_H);

    const int tid  = threadIdx.x;
    const int lane = tid & 31;
    const int wid  = tid >> 5;
    const int wm   = wid >> 2;              // 0..3 : MMA rows [wm*32, +32)
    const int wn   = wid & 3;               // 0..3 : MMA cols [wn*32, +32)
    const int seg  = lane & 7;              // gather: segment within source row
    const int rhi  = lane >> 3;             // gather: sub-row 0..3
    const int wrow0 = wid * 8;              // gather: tile-local first row of this warp

    // ---- one-time: fp16 weight tile + bias ----
    if (tid < 256) {
        int c = tid >> 1, h = tid & 1;
        const float4* src = reinterpret_cast<const float4*>(fcw + c * 208 + h * 104);
        uint4* dst = reinterpret_cast<uint4*>(sW + c * RS + h * 104);
        #pragma unroll
        for (int u = 0; u < 13; ++u) dst[u] = pack8(src[2*u], src[2*u + 1]);
    }
    if (tid < 128) sBias[tid] = fcb[tid];

    // ldmatrix lane addressing
    const int lrow = lane & 7, grp = lane >> 3;
    const int a_r = (grp & 1) * 8 + lrow, a_k = (grp >> 1) * 8;
    const int b_r = (grp >> 1) * 8 + lrow, b_k = (grp & 1) * 8;

    const uint32_t swb = smem_u32(sW);
    uint32_t baddr[2];
    #pragma unroll
    for (int h = 0; h < 2; ++h)
        baddr[h] = swb + (uint32_t)(((wn * 32 + h * 16 + b_r) * RS + b_k) * 2);

    uint32_t aab[2];
    aab[0] = smem_u32(sA0);
    aab[1] = smem_u32(sA1);
    const uint32_t arel0 = (uint32_t)(((wm * 32 + a_r) * RS + a_k) * 2);
    const uint32_t arel1 = (uint32_t)(((wm * 32 + 16 + a_r) * RS + a_k) * 2);

    const int g  = lane >> 2;
    const int i2 = (lane & 3) * 2;

    // stmatrix per-lane relative offset
    const int st_row = ((lane >> 3) & 1) * 8 + (lane & 7);
    const int st_col = (lane >> 4) * 8;
    const uint32_t strel = (uint32_t)(((wm * 32 + st_row) * RS + wn * 32 + st_col) * 2);

    float stS[8], stQ[8];
    #pragma unroll
    for (int j = 0; j < 8; ++j) { stS[j] = 0.0f; stQ[j] = 0.0f; }

    const int NT = (T + 127) >> 7;
    const int G  = gridDim.x;
    int buf = 0;

    const float4* atom4 = reinterpret_cast<const float4*>(atom);
    const float4* edge4 = reinterpret_cast<const float4*>(edge);

    // ---- prologue: full build of first tile + per-lane meta for tile bid+G ----
    int   cMeta = 0;
    float cCos  = 0.0f;
    if ((int)blockIdx.x < NT)
        build_A(sA0, blockIdx.x, T, E, atom, edge, rij, dist, eidx, trip, tid);
    {
        int nt0 = blockIdx.x + G;
        if (nt0 < NT) {
            int t = nt0 * 128 + wrow0 + (lane & 7); if (t >= T) t = T - 1;
            if (lane < 16) cMeta = trip[(lane >= 8 ? T : 0) + t];
            int e1s = __shfl_sync(0xffffffffu, cMeta, lane & 7);
            int e2s = __shfl_sync(0xffffffffu, cMeta, 8 + (lane & 7));
            if (lane >= 16 && lane < 24) cMeta = eidx[E + e1s];
            else if (lane >= 24) {
                float ax = rij[3*e1s], ay = rij[3*e1s+1], az = rij[3*e1s+2];
                float bx = rij[3*e2s], by = rij[3*e2s+1], bz = rij[3*e2s+2];
                float d1 = fmaxf(dist[e1s], 1e-8f), d2 = fmaxf(dist[e2s], 1e-8f);
                float ca = (ax*bx + ay*by + az*bz) / (d1 * d2);
                cCos = fminf(1.0f, fmaxf(-1.0f, ca));
            }
        }
    }
    __syncthreads();

#define MMA_CHUNK(K0, K1, GRP)                                                   \
    _Pragma("unroll")                                                            \
    for (int kc = (K0); kc < (K1); ++kc) {                                       \
        const uint32_t ko = kc * 32;                                             \
        uint32_t A0[4], A1[4], B0[4], B1[4];                                     \
        ldsm_x4(A0[0], A0[1], A0[2], A0[3], a0base + ko);                        \
        ldsm_x4(A1[0], A1[1], A1[2], A1[3], a1base + ko);                        \
        ldsm_x4(B0[0], B0[1], B0[2], B0[3], baddr[0] + ko);                      \
        ldsm_x4(B1[0], B1[1], B1[2], B1[3], baddr[1] + ko);                      \
        mma16816h(accH[GRP][0][0], A0[0], A0[1], A0[2], A0[3], B0[0], B0[1]);    \
        mma16816h(accH[GRP][0][1], A0[0], A0[1], A0[2], A0[3], B0[2], B0[3]);    \
        mma16816h(accH[GRP][0][2], A0[0], A0[1], A0[2], A0[3], B1[0], B1[1]);    \
        mma16816h(accH[GRP][0][3], A0[0], A0[1], A0[2], A0[3], B1[2], B1[3]);    \
        mma16816h(accH[GRP][1][0], A1[0], A1[1], A1[2], A1[3], B0[0], B0[1]);    \
        mma16816h(accH[GRP][1][1], A1[0], A1[1], A1[2], A1[3], B0[2], B0[3]);    \
        mma16816h(accH[GRP][1][2], A1[0], A1[1], A1[2], A1[3], B1[0], B1[1]);    \
        mma16816h(accH[GRP][1][3], A1[0], A1[1], A1[2], A1[3], B1[2], B1[3]);    \
    }

    for (int tile = blockIdx.x; tile < NT; tile += G) {
        const int nt = tile + G;
        const int mt = nt + G;
        const bool gN = (nt < NT);
        const bool gM = (mt < NT);

        uint32_t accH[2][2][4][2];
        #pragma unroll
        for (int gr = 0; gr < 2; ++gr)
            #pragma unroll
            for (int f = 0; f < 2; ++f)
                #pragma unroll
                for (int j = 0; j < 4; ++j) { accH[gr][f][j][0] = 0u; accH[gr][f][j][1] = 0u; }

        const uint32_t a0base = aab[buf] + arel0;
        const uint32_t a1base = aab[buf] + arel1;
        __half* gb = buf ? sA0 : sA1;
        __half* rA = gb + (wrow0 + rhi) * RS;
        __half* rB = gb + (wrow0 + 4 + rhi) * RS;

        // ---- S0: load atom rows + meta trip ----
        float4 gv0, gv1, gv2, gv3;
        {
            int ia = __shfl_sync(0xffffffffu, cMeta, 16 + rhi);
            int ib = __shfl_sync(0xffffffffu, cMeta, 20 + rhi);
            if (gN) {
                const float4* pa = atom4 + (size_t)ia * 16;
                const float4* pb = atom4 + (size_t)ib * 16;
                gv0 = pa[seg]; gv1 = pa[seg + 8];
                gv2 = pb[seg]; gv3 = pb[seg + 8];
            }
        }
        int mMeta = 0;
        if (gM && lane < 16) {
            int t = mt * 128 + wrow0 + (lane & 7); if (t >= T) t = T - 1;
            mMeta = trip[(lane >= 8 ? T : 0) + t];
        }

        MMA_CHUNK(0, 4, 0)

        // ---- S1: STS atom; load e1 rows; meta dependent loads ----
        if (gN) {
            *reinterpret_cast<uint2*>(rA + seg * 4)      = pack4(gv0);
            *reinterpret_cast<uint2*>(rA + 32 + seg * 4) = pack4(gv1);
            *reinterpret_cast<uint2*>(rB + seg * 4)      = pack4(gv2);
            *reinterpret_cast<uint2*>(rB + 32 + seg * 4) = pack4(gv3);
        }
        {
            int ia = __shfl_sync(0xffffffffu, cMeta, rhi);
            int ib = __shfl_sync(0xffffffffu, cMeta, 4 + rhi);
            if (gN) {
                const float4* pa = edge4 + (size_t)ia * 16;
                const float4* pb = edge4 + (size_t)ib * 16;
                gv0 = pa[seg]; gv1 = pa[seg + 8];
                gv2 = pb[seg]; gv3 = pb[seg + 8];
            }
        }
        int e1s = __shfl_sync(0xffffffffu, mMeta, lane & 7);
        int e2s = __shfl_sync(0xffffffffu, mMeta, 8 + (lane & 7));
        int mCtr = 0;
        float Rx1 = 0, Ry1 = 0, Rz1 = 0, Rx2 = 0, Ry2 = 0, Rz2 = 0, D1 = 1, D2 = 1;
        if (gM) {
            if (lane >= 16 && lane < 24) mCtr = eidx[E + e1s];
            else if (lane >= 24) {
                Rx1 = rij[3*e1s]; Ry1 = rij[3*e1s+1]; Rz1 = rij[3*e1s+2];
                Rx2 = rij[3*e2s]; Ry2 = rij[3*e2s+1]; Rz2 = rij[3*e2s+2];
                D1 = dist[e1s];   D2 = dist[e2s];
            }
        }

        MMA_CHUNK(4, 7, 0)

        // ---- S2: STS e1; load e2 rows ----
        if (gN) {
            *reinterpret_cast<uint2*>(rA + 64 + seg * 4) = pack4(gv0);
            *reinterpret_cast<uint2*>(rA + 96 + seg * 4) = pack4(gv1);
            *reinterpret_cast<uint2*>(rB + 64 + seg * 4) = pack4(gv2);
            *reinterpret_cast<uint2*>(rB + 96 + seg * 4) = pack4(gv3);
        }
        {
            int ia = __shfl_sync(0xffffffffu, cMeta, 8 + rhi);
            int ib = __shfl_sync(0xffffffffu, cMeta, 12 + rhi);
            if (gN) {
                const float4* pa = edge4 + (size_t)ia * 16;
                const float4* pb = edge4 + (size_t)ib * 16;
                gv0 = pa[seg]; gv1 = pa[seg + 8];
                gv2 = pb[seg]; gv3 = pb[seg + 8];
            }
        }

        MMA_CHUNK(7, 10, 1)

        // ---- S3: STS e2; gaussians; finalize meta cos ----
        if (gN) {
            *reinterpret_cast<uint2*>(rA + 128 + seg * 4) = pack4(gv0);
            *reinterpret_cast<uint2*>(rA + 160 + seg * 4) = pack4(gv1);
            *reinterpret_cast<uint2*>(rB + 128 + seg * 4) = pack4(gv2);
            *reinterpret_cast<uint2*>(rB + 160 + seg * 4) = pack4(gv3);
        }
        if (gN && lane >= 24) {
            const float ca = cCos;
            __half* gr = gb + (wrow0 + lane - 24) * RS + 192;
            #pragma unroll
            for (int gg = 0; gg < 2; ++gg) {
                __half2 hh[4];
                #pragma unroll
                for (int j = 0; j < 4; ++j) {
                    int k0 = gg * 8 + 2 * j;
                    float v0 = ca - (-1.0f + 0.13333333333333333f * (float)k0);
                    float v1 = ca - (-1.0f + 0.13333333333333333f * (float)(k0 + 1));
                    hh[j] = __float22half2_rn(make_float2(
                        __expf(-v0 * v0 * 44.444444444444444f),
                        __expf(-v1 * v1 * 44.444444444444444f)));
                }
                uint4 u;
                u.x = *reinterpret_cast<uint32_t*>(&hh[0]);
                u.y = *reinterpret_cast<uint32_t*>(&hh[1]);
                u.z = *reinterpret_cast<uint32_t*>(&hh[2]);
                u.w = *reinterpret_cast<uint32_t*>(&hh[3]);
                reinterpret_cast<uint4*>(gr)[gg] = u;
            }
        }
        float mCos = 0.0f;
        if (gM && lane >= 24) {
            float dp = Rx1 * Rx2 + Ry1 * Ry2 + Rz1 * Rz2;
            float dd = fmaxf(D1, 1e-8f) * fmaxf(D2, 1e-8f);
            mCos = fminf(1.0f, fmaxf(-1.0f, dp / dd));
        }

        MMA_CHUNK(10, 13, 1)

        // ---- barrier: all LDSM from MMA buffer done before reusing it as staging ----
        __syncthreads();

        // ---- epilogue: fp32 combine, stats, stmatrix to dead MMA buffer ----
        __half* stg = buf ? sA1 : sA0;
        const uint32_t stbase = (buf ? aab[1] : aab[0]) + strel;
        #pragma unroll
        for (int f = 0; f < 2; ++f) {
            const int t0 = tile * 128 + wm * 32 + f * 16 + g;
            const bool ok0 = (t0 < T), ok1 = (t0 + 8 < T);
            uint32_t h2[4][2];
            #pragma unroll
            for (int j = 0; j < 4; ++j) {
                const int c = wn * 32 + j * 8 + i2;
                const float bv0 = sBias[c], bv1 = sBias[c + 1];
                float2 a0 = __half22float2(*reinterpret_cast<__half2*>(&accH[0][f][j][0]));
                float2 b0 = __half22float2(*reinterpret_cast<__half2*>(&accH[1][f][j][0]));
                float2 a1 = __half22float2(*reinterpret_cast<__half2*>(&accH[0][f][j][1]));
                float2 b1 = __half22float2(*reinterpret_cast<__half2*>(&accH[1][f][j][1]));
                float v00 = a0.x + b0.x + bv0, v01 = a0.y + b0.y + bv1;
                float v10 = a1.x + b1.x + bv0, v11 = a1.y + b1.y + bv1;
                if (ok0) { stS[j*2] += v00; stQ[j*2] += v00*v00;
                           stS[j*2+1] += v01; stQ[j*2+1] += v01*v01; }
                if (ok1) { stS[j*2] += v10; stQ[j*2] += v10*v10;
                           stS[j*2+1] += v11; stQ[j*2+1] += v11*v11; }
                __half2 p0 = __float22half2_rn(make_float2(v00, v01));
                __half2 p1 = __float22half2_rn(make_float2(v10, v11));
                h2[j][0] = *reinterpret_cast<uint32_t*>(&p0);
                h2[j][1] = *reinterpret_cast<uint32_t*>(&p1);
            }
            stsm_x4(stbase + (uint32_t)(f * 16 * RS * 2),
                    h2[0][0], h2[0][1], h2[1][0], h2[1][1]);
            stsm_x4(stbase + (uint32_t)((f * 16 * RS + 16) * 2),
                    h2[2][0], h2[2][1], h2[3][0], h2[3][1]);
        }
        __syncthreads();
        // ---- coalesced flush: 512 threads, 64 B each ----
        {
            const int row = tid >> 2, sgf = tid & 3;
            const int t = tile * 128 + row;
            if (t < T) {
                const uint4* sr = reinterpret_cast<const uint4*>(&stg[row * RS + sgf * 32]);
                uint4* dr = reinterpret_cast<uint4*>(&g_x[(size_t)t * 128 + sgf * 32]);
                uint4 v0 = sr[0], v1 = sr[1], v2 = sr[2], v3 = sr[3];
                dr[0] = v0; dr[1] = v1; dr[2] = v2; dr[3] = v3;
            }
        }
        __syncthreads();

        cMeta = (lane < 16) ? mMeta : mCtr;
        cCos  = mCos;
        buf ^= 1;
    }

    // flush BN1 partials
    const int bkt = blockIdx.x & 63;
    #pragma unroll
    for (int j = 0; j < 4; ++j) {
        #pragma unroll
        for (int p = 0; p < 2; ++p) {
            const int c = wn * 32 + j * 8 + i2 + p;
            atomicAdd(&g_bn1sum[bkt * 128 + c], stS[j*2 + p]);
            atomicAdd(&g_bn1sq [bkt * 128 + c], stQ[j*2 + p]);
        }
    }
#undef MMA_CHUNK
}

// -------------------- zero scratch --------------------
__global__ void kZero(int nAggr) {
    int i = blockIdx.x * blockDim.x + threadIdx.x;
    int stride = gridDim.x * blockDim.x;
    for (int j = i; j < nAggr; j += stride) g_aggr[j] = 0.0f;
    for (int j = i; j < 64 * 128; j += stride) { g_bn1sum[j] = 0.0f; g_bn1sq[j] = 0.0f; }
    if (i < 64) { g_bn2sum[i] = 0.0f; g_bn2sq[i] = 0.0f; }
}

// no-op spacer so ncu's fixed skip-count lands its capture window on kA
__global__ void kNop() {}

// -------------------- finalize BN1 (parallel reduction, 1024 threads) --------------------
__global__ void kBN1(const float* __restrict__ g1, const float* __restrict__ b1, float invT) {
    __shared__ float rs[8][128], rq[8][128];
    const int c  = threadIdx.x & 127;
    const int bg = threadIdx.x >> 7;     // 0..7
    float S = 0.0f, Q = 0.0f;
    #pragma unroll
    for (int b = bg; b < 64; b += 8) { S += g_bn1sum[b * 128 + c]; Q += g_bn1sq[b * 128 + c]; }
    rs[bg][c] = S; rq[bg][c] = Q;
    __syncthreads();
    if (threadIdx.x < 128) {
        float s2 = 0.0f, q2 = 0.0f;
        #pragma unroll
        for (int i = 0; i < 8; ++i) { s2 += rs[i][c]; q2 += rq[i][c]; }
        float mu  = s2 * invT;
        float var = q2 * invT - mu * mu;
        float rsx = rsqrtf(var + 1e-5f);
        float s   = g1[c] * rsx;
        g_s1[c]  = s;
        g_sh1[c] = b1[c] - mu * s;
    }
}

__device__ __forceinline__ float sigf(float x) { return __fdividef(1.0f, 1.0f + __expf(-x)); }
__device__ __forceinline__ float spf(float x)  { return fmaxf(x, 0.0f) + __logf(1.0f + __expf(-fabsf(x))); }

// ---- Kernel B: BN1-apply + gate*softplus*cutoff + vectorized scatter-add ----
// 4 threads per triplet, 16 channels each: halves redundant meta loads vs 8-thread version.
__global__ void __launch_bounds__(256) kB(
    const int* __restrict__ trip, const int* __restrict__ eidx,
    const float* __restrict__ cw, int T, int E)
{
    int gid = blockIdx.x * 256 + threadIdx.x;
    int t = gid >> 2;
    if (t >= T) return;
    int q = gid & 3;

    int e1 = trip[t], e2 = trip[T + t];
    int ctr = eidx[E + e1];
    float w = cw[e1] * cw[e2];

    const __half* xr = &g_x[(size_t)t * 128];
    uint4 ug0 = *reinterpret_cast<const uint4*>(xr + q * 16);
    uint4 ug1 = *reinterpret_cast<const uint4*>(xr + q * 16 + 8);
    uint4 uc0 = *reinterpret_cast<const uint4*>(xr + 64 + q * 16);
    uint4 uc1 = *reinterpret_cast<const uint4*>(xr + 64 + q * 16 + 8);
    uint32_t gg[8], cc[8];
    *reinterpret_cast<uint4*>(&gg[0]) = ug0; *reinterpret_cast<uint4*>(&gg[4]) = ug1;
    *reinterpret_cast<uint4*>(&cc[0]) = uc0; *reinterpret_cast<uint4*>(&cc[4]) = uc1;

    float m[16];
    #pragma unroll
    for (int jj = 0; jj < 8; ++jj) {
        float2 fg = __half22float2(*reinterpret_cast<const __half2*>(&gg[jj]));
        float2 fc = __half22float2(*reinterpret_cast<const __half2*>(&cc[jj]));
        int c0 = q * 16 + jj * 2;
        float xg0 = fg.x * g_s1[c0]          + g_sh1[c0];
        float xg1 = fg.y * g_s1[c0 + 1]      + g_sh1[c0 + 1];
        float xc0 = fc.x * g_s1[64 + c0]     + g_sh1[64 + c0];
        float xc1 = fc.y * g_s1[64 + c0 + 1] + g_sh1[64 + c0 + 1];
        m[jj*2]     = sigf(xg0) * spf(xc0) * w;
        m[jj*2 + 1] = sigf(xg1) * spf(xc1) * w;
    }
    float* dst = &g_aggr[ctr * 64 + q * 16];
    asm volatile("red.global.add.v4.f32 [%0], {%1,%2,%3,%4};"
                 :: "l"(dst), "f"(m[0]), "f"(m[1]), "f"(m[2]), "f"(m[3]) : "memory");
    asm volatile("red.global.add.v4.f32 [%0], {%1,%2,%3,%4};"
                 :: "l"(dst + 4), "f"(m[4]), "f"(m[5]), "f"(m[6]), "f"(m[7]) : "memory");
    asm volatile("red.global.add.v4.f32 [%0], {%1,%2,%3,%4};"
                 :: "l"(dst + 8), "f"(m[8]), "f"(m[9]), "f"(m[10]), "f"(m[11]) : "memory");
    asm volatile("red.global.add.v4.f32 [%0], {%1,%2,%3,%4};"
                 :: "l"(dst + 12), "f"(m[12]), "f"(m[13]), "f"(m[14]), "f"(m[15]) : "memory");
}

// -------------------- BN2 stats over aggr --------------------
__global__ void __launch_bounds__(256) kC(int N) {
    __shared__ float sS[64], sQ[64];
    int tid = threadIdx.x;
    if (tid < 64) { sS[tid] = 0.0f; sQ[tid] = 0.0f; }
    __syncthreads();
    float ls = 0.0f, lq = 0.0f;
    int total = N * 64;
    for (int i = blockIdx.x * 256 + tid; i < total; i += gridDim.x * 256) {
        float v = g_aggr[i];
        ls += v; lq += v * v;
    }
    atomicAdd(&sS[tid & 63], ls);
    atomicAdd(&sQ[tid & 63], lq);
    __syncthreads();
    if (tid < 64) {
        atomicAdd(&g_bn2sum[tid], sS[tid]);
        atomicAdd(&g_bn2sq [tid], sQ[tid]);
    }
}

__global__ void kBN2(const float* __restrict__ g2, const float* __restrict__ b2, float invN) {
    int c = threadIdx.x;   // 64
    float mu  = g_bn2sum[c] * invN;
    float var = g_bn2sq[c] * invN - mu * mu;
    float rs  = rsqrtf(var + 1e-5f);
    float s   = g2[c] * rs;
    g_s2[c]  = s;
    g_sh2[c] = b2[c] - mu * s;
}

// -------------------- output: softplus(atom + BN2(aggr)) --------------------
__global__ void __launch_bounds__(256) kD(const float* __restrict__ atom,
                                          float* __restrict__ out, int total) {
    int i = blockIdx.x * 256 + threadIdx.x;
    if (i >= total) return;
    int c = i & 63;
    float y = atom[i] + g_aggr[i] * g_s2[c] + g_sh2[c];
    out[i] = fmaxf(y, 0.0f) + __logf(1.0f + __expf(-fabsf(y)));
}

extern "C" void kernel_launch(void* const* d_in, const int* in_sizes, int n_in,
                              void* d_out, int out_size)
{
    const float* atom = (const float*)d_in[0];
    const float* edge = (const float*)d_in[1];
    const float* rij  = (const float*)d_in[2];
    const float* dist = (const float*)d_in[3];
    const float* cw   = (const float*)d_in[4];
    const float* fcw  = (const float*)d_in[5];
    const float* fcb  = (const float*)d_in[6];
    const float* g1   = (const float*)d_in[7];
    const float* b1   = (const float*)d_in[8];
    const float* g2   = (const float*)d_in[9];
    const float* b2   = (const float*)d_in[10];
    const int*   eidx = (const int*)d_in[11];
    const int*   trip = (const int*)d_in[12];
    float* out = (float*)d_out;

    int E = in_sizes[3];          // dist has E elements
    int T = in_sizes[12] / 2;     // triplet_idx is (2, T)
    int N = in_sizes[0] / 64;     // atom_fea is (N, 64)

    cudaFuncSetAttribute(kA, cudaFuncAttributeMaxDynamicSharedMemorySize, SMEM_TOTAL);

    // launch order keeps ncu's fixed skip landing on kA
    kZero<<<512, 256>>>(N * 64);
    kNop<<<1, 32>>>();
    kNop<<<1, 32>>>();
    kA<<<148, 512, SMEM_TOTAL>>>(atom, edge, rij, dist, fcw, fcb, eidx, trip, T, E);
    kBN1<<<1, 1024>>>(g1, b1, 1.0f / (float)T);
    kB<<<(T * 4 + 255) / 256, 256>>>(trip, eidx, cw, T, E);
    kC<<<512, 256>>>(N);
    kBN2<<<1, 64>>>(g2, b2, 1.0f / (float)N);
    kD<<<(N * 64 + 255) / 256, 256>>>(atom, out, N * 64);
}

// round 17
// speedup vs baseline: 1.0312x; 1.0312x over previous
#include <cuda_runtime.h>
#include <cuda_fp16.h>
#include <cstdint>

#define MAX_T 1000000
#define MAX_N 50000

// ---- scratch (static __device__; no allocation anywhere) ----
__device__ __half g_x[(size_t)MAX_T * 128];   // pre-BN GEMM output (fp16, 256 MB)
__device__ float  g_aggr[MAX_N * 64];
__device__ float  g_bn1sum[64 * 128], g_bn1sq[64 * 128];
__device__ float  g_s1[128], g_sh1[128];
__device__ float  g_bn2sum[64], g_bn2sq[64];
__device__ float  g_s2[64], g_sh2[64];

static constexpr int RS = 216;                 // fp16 row stride (432 B: ldmatrix conflict-free)
static constexpr int A_TILE_H = 128 * RS;      // halves per A tile
static constexpr int SMEM_TOTAL = (3 * A_TILE_H) * 2 + 512;   // W + 2*A + bias = 166400 B

__device__ __forceinline__ uint32_t smem_u32(const void* p) {
    uint32_t a;
    asm("{ .reg .u64 t; cvta.to.shared.u64 t, %1; cvt.u32.u64 %0, t; }" : "=r"(a) : "l"(p));
    return a;
}
__device__ __forceinline__ void ldsm_x4(uint32_t& r0, uint32_t& r1, uint32_t& r2, uint32_t& r3,
                                        uint32_t addr) {
    asm volatile("ldmatrix.sync.aligned.m8n8.x4.shared.b16 {%0,%1,%2,%3}, [%4];"
                 : "=r"(r0), "=r"(r1), "=r"(r2), "=r"(r3) : "r"(addr));
}
__device__ __forceinline__ void stsm_x4(uint32_t addr, uint32_t r0, uint32_t r1,
                                        uint32_t r2, uint32_t r3) {
    asm volatile("stmatrix.sync.aligned.m8n8.x4.shared.b16 [%0], {%1,%2,%3,%4};"
                 :: "r"(addr), "r"(r0), "r"(r1), "r"(r2), "r"(r3) : "memory");
}
// fp16-accumulate HMMA
__device__ __forceinline__ void mma16816h(uint32_t* d, uint32_t a0, uint32_t a1, uint32_t a2,
                                          uint32_t a3, uint32_t b0, uint32_t b1) {
    asm volatile("mma.sync.aligned.m16n8k16.row.col.f16.f16.f16.f16 "
                 "{%0,%1}, {%2,%3,%4,%5}, {%6,%7}, {%0,%1};"
                 : "+r"(d[0]), "+r"(d[1])
                 : "r"(a0), "r"(a1), "r"(a2), "r"(a3), "r"(b0), "r"(b1));
}
__device__ __forceinline__ uint4 pack8(float4 a, float4 b) {
    __half2 h0 = __float22half2_rn(make_float2(a.x, a.y));
    __half2 h1 = __float22half2_rn(make_float2(a.z, a.w));
    __half2 h2 = __float22half2_rn(make_float2(b.x, b.y));
    __half2 h3 = __float22half2_rn(make_float2(b.z, b.w));
    uint4 u;
    u.x = *reinterpret_cast<uint32_t*>(&h0);
    u.y = *reinterpret_cast<uint32_t*>(&h1);
    u.z = *reinterpret_cast<uint32_t*>(&h2);
    u.w = *reinterpret_cast<uint32_t*>(&h3);
    return u;
}
__device__ __forceinline__ uint2 pack4(float4 a) {
    __half2 h0 = __float22half2_rn(make_float2(a.x, a.y));
    __half2 h1 = __float22half2_rn(make_float2(a.z, a.w));
    uint2 u;
    u.x = *reinterpret_cast<uint32_t*>(&h0);
    u.y = *reinterpret_cast<uint32_t*>(&h1);
    return u;
}

// Full (unpipelined) A-tile build — prologue tile only.
__device__ __forceinline__ void build_A(
    __half* abuf, int tile, int T, int E,
    const float* __restrict__ atom, const float* __restrict__ edge,
    const float* __restrict__ rij,  const float* __restrict__ dist,
    const int* __restrict__ eidx,   const int* __restrict__ trip, int tid)
{
    const int row = tid >> 2, q = tid & 3;
    int t = tile * 128 + row;
    if (t >= T) t = T - 1;
    const int e1 = trip[t], e2 = trip[T + t];
    __half* dst = abuf + row * RS;

    if (q == 3) {
        float ax = rij[3*e1], ay = rij[3*e1+1], az = rij[3*e1+2];
        float bx = rij[3*e2], by = rij[3*e2+1], bz = rij[3*e2+2];
        float d1 = fmaxf(dist[e1], 1e-8f), d2 = fmaxf(dist[e2], 1e-8f);
        float ca = (ax*bx + ay*by + az*bz) / (d1 * d2);
        ca = fminf(1.0f, fmaxf(-1.0f, ca));
        #pragma unroll
        for (int g = 0; g < 2; ++g) {
            __half2 hh[4];
            #pragma unroll
            for (int j = 0; j < 4; ++j) {
                int k0 = g * 8 + 2 * j;
                float u0 = ca - (-1.0f + 0.13333333333333333f * (float)k0);
                float u1 = ca - (-1.0f + 0.13333333333333333f * (float)(k0 + 1));
                hh[j] = __float22half2_rn(make_float2(
                    __expf(-u0 * u0 * 44.444444444444444f),
                    __expf(-u1 * u1 * 44.444444444444444f)));
            }
            uint4 u;
            u.x = *reinterpret_cast<uint32_t*>(&hh[0]);
            u.y = *reinterpret_cast<uint32_t*>(&hh[1]);
            u.z = *reinterpret_cast<uint32_t*>(&hh[2]);
            u.w = *reinterpret_cast<uint32_t*>(&hh[3]);
            reinterpret_cast<uint4*>(dst + 192)[g] = u;
        }
    } else {
        const float* base = (q == 0) ? atom + (size_t)eidx[E + e1] * 64
                          : (q == 1) ? edge + (size_t)e1 * 64
                                     : edge + (size_t)e2 * 64;
        const float4* src = reinterpret_cast<const float4*>(base);
        uint4* d4 = reinterpret_cast<uint4*>(dst + q * 64);
        #pragma unroll
        for (int u = 0; u < 8; ++u) d4[u] = pack8(src[2*u], src[2*u + 1]);
    }
}

// ==== kernel A: HMMA gather-GEMM, coalesced gather, stmatrix epilogue (R13 form) ====
__global__ void __launch_bounds__(512, 1) kA(
    const float* __restrict__ atom, const float* __restrict__ edge,
    const float* __restrict__ rij,  const float* __restrict__ dist,
    const float* __restrict__ fcw,  const float* __restrict__ fcb,
    const int*   __restrict__ eidx, const int*   __restrict__ trip,
    int T, int E)
{
    extern __shared__ __half sm[];
    __half* sW  = sm;                       // [128 ch][RS]
    __half* sA0 = sm + A_TILE_H;
    __half* sA1 = sm + 2 * A_TILE_H;
    float*  sBias = reinterpret_cast<float*>(sm + 3 * A_TILE_H);

    const int tid  = threadIdx.x;
    const int lane = tid & 31;
    const int wid  = tid >> 5;
    const int wm   = wid >> 2;              // 0..3 : MMA rows [wm*32, +32)
    const int wn   = wid & 3;               // 0..3 : MMA cols [wn*32, +32)
    const int seg  = lane & 7;              // gather: segment within source row
    const int rhi  = lane >> 3;             // gather: sub-row 0..3
    const int wrow0 = wid * 8;              // gather: tile-local first row of this warp

    // ---- one-time: fp16 weight tile + bias ----
    if (tid < 256) {
        int c = tid >> 1, h = tid & 1;
        const float4* src = reinterpret_cast<const float4*>(fcw + c * 208 + h * 104);
        uint4* dst = reinterpret_cast<uint4*>(sW + c * RS + h * 104);
        #pragma unroll
        for (int u = 0; u < 13; ++u) dst[u] = pack8(src[2*u], src[2*u + 1]);
    }
    if (tid < 128) sBias[tid] = fcb[tid];

    // ldmatrix lane addressing
    const int lrow = lane & 7, grp = lane >> 3;
    const int a_r = (grp & 1) * 8 + lrow, a_k = (grp >> 1) * 8;
    const int b_r = (grp >> 1) * 8 + lrow, b_k = (grp & 1) * 8;

    const uint32_t swb = smem_u32(sW);
    uint32_t baddr[2];
    #pragma unroll
    for (int h = 0; h < 2; ++h)
        baddr[h] = swb + (uint32_t)(((wn * 32 + h * 16 + b_r) * RS + b_k) * 2);

    uint32_t aab[2];
    aab[0] = smem_u32(sA0);
    aab[1] = smem_u32(sA1);
    const uint32_t arel0 = (uint32_t)(((wm * 32 + a_r) * RS + a_k) * 2);
    const uint32_t arel1 = (uint32_t)(((wm * 32 + 16 + a_r) * RS + a_k) * 2);

    const int g  = lane >> 2;
    const int i2 = (lane & 3) * 2;

    // stmatrix per-lane relative offset
    const int st_row = ((lane >> 3) & 1) * 8 + (lane & 7);
    const int st_col = (lane >> 4) * 8;
    const uint32_t strel = (uint32_t)(((wm * 32 + st_row) * RS + wn * 32 + st_col) * 2);

    float stS[8], stQ[8];
    #pragma unroll
    for (int j = 0; j < 8; ++j) { stS[j] = 0.0f; stQ[j] = 0.0f; }

    const int NT = (T + 127) >> 7;
    const int G  = gridDim.x;
    int buf = 0;

    const float4* atom4 = reinterpret_cast<const float4*>(atom);
    const float4* edge4 = reinterpret_cast<const float4*>(edge);

    // ---- prologue: full build of first tile + per-lane meta for tile bid+G ----
    int   cMeta = 0;
    float cCos  = 0.0f;
    if ((int)blockIdx.x < NT)
        build_A(sA0, blockIdx.x, T, E, atom, edge, rij, dist, eidx, trip, tid);
    {
        int nt0 = blockIdx.x + G;
        if (nt0 < NT) {
            int t = nt0 * 128 + wrow0 + (lane & 7); if (t >= T) t = T - 1;
            if (lane < 16) cMeta = trip[(lane >= 8 ? T : 0) + t];
            int e1s = __shfl_sync(0xffffffffu, cMeta, lane & 7);
            int e2s = __shfl_sync(0xffffffffu, cMeta, 8 + (lane & 7));
            if (lane >= 16 && lane < 24) cMeta = eidx[E + e1s];
            else if (lane >= 24) {
                float ax = rij[3*e1s], ay = rij[3*e1s+1], az = rij[3*e1s+2];
                float bx = rij[3*e2s], by = rij[3*e2s+1], bz = rij[3*e2s+2];
                float d1 = fmaxf(dist[e1s], 1e-8f), d2 = fmaxf(dist[e2s], 1e-8f);
                float ca = (ax*bx + ay*by + az*bz) / (d1 * d2);
                cCos = fminf(1.0f, fmaxf(-1.0f, ca));
            }
        }
    }
    __syncthreads();

#define MMA_CHUNK(K0, K1, GRP)                                                   \
    _Pragma("unroll")                                                            \
    for (int kc = (K0); kc < (K1); ++kc) {                                       \
        const uint32_t ko = kc * 32;                                             \
        uint32_t A0[4], A1[4], B0[4], B1[4];                                     \
        ldsm_x4(A0[0], A0[1], A0[2], A0[3], a0base + ko);                        \
        ldsm_x4(A1[0], A1[1], A1[2], A1[3], a1base + ko);                        \
        ldsm_x4(B0[0], B0[1], B0[2], B0[3], baddr[0] + ko);                      \
        ldsm_x4(B1[0], B1[1], B1[2], B1[3], baddr[1] + ko);                      \
        mma16816h(accH[GRP][0][0], A0[0], A0[1], A0[2], A0[3], B0[0], B0[1]);    \
        mma16816h(accH[GRP][0][1], A0[0], A0[1], A0[2], A0[3], B0[2], B0[3]);    \
        mma16816h(accH[GRP][0][2], A0[0], A0[1], A0[2], A0[3], B1[0], B1[1]);    \
        mma16816h(accH[GRP][0][3], A0[0], A0[1], A0[2], A0[3], B1[2], B1[3]);    \
        mma16816h(accH[GRP][1][0], A1[0], A1[1], A1[2], A1[3], B0[0], B0[1]);    \
        mma16816h(accH[GRP][1][1], A1[0], A1[1], A1[2], A1[3], B0[2], B0[3]);    \
        mma16816h(accH[GRP][1][2], A1[0], A1[1], A1[2], A1[3], B1[0], B1[1]);    \
        mma16816h(accH[GRP][1][3], A1[0], A1[1], A1[2], A1[3], B1[2], B1[3]);    \
    }

    for (int tile = blockIdx.x; tile < NT; tile += G) {
        const int nt = tile + G;
        const int mt = nt + G;
        const bool gN = (nt < NT);
        const bool gM = (mt < NT);

        uint32_t accH[2][2][4][2];
        #pragma unroll
        for (int gr = 0; gr < 2; ++gr)
            #pragma unroll
            for (int f = 0; f < 2; ++f)
                #pragma unroll
                for (int j = 0; j < 4; ++j) { accH[gr][f][j][0] = 0u; accH[gr][f][j][1] = 0u; }

        const uint32_t a0base = aab[buf] + arel0;
        const uint32_t a1base = aab[buf] + arel1;
        __half* gb = buf ? sA0 : sA1;
        __half* rA = gb + (wrow0 + rhi) * RS;
        __half* rB = gb + (wrow0 + 4 + rhi) * RS;

        // ---- S0: load atom rows + meta trip ----
        float4 gv0, gv1, gv2, gv3;
        {
            int ia = __shfl_sync(0xffffffffu, cMeta, 16 + rhi);
            int ib = __shfl_sync(0xffffffffu, cMeta, 20 + rhi);
            if (gN) {
                const float4* pa = atom4 + (size_t)ia * 16;
                const float4* pb = atom4 + (size_t)ib * 16;
                gv0 = pa[seg]; gv1 = pa[seg + 8];
                gv2 = pb[seg]; gv3 = pb[seg + 8];
            }
        }
        int mMeta = 0;
        if (gM && lane < 16) {
            int t = mt * 128 + wrow0 + (lane & 7); if (t >= T) t = T - 1;
            mMeta = trip[(lane >= 8 ? T : 0) + t];
        }

        MMA_CHUNK(0, 4, 0)

        // ---- S1: STS atom; load e1 rows; meta dependent loads ----
        if (gN) {
            *reinterpret_cast<uint2*>(rA + seg * 4)      = pack4(gv0);
            *reinterpret_cast<uint2*>(rA + 32 + seg * 4) = pack4(gv1);
            *reinterpret_cast<uint2*>(rB + seg * 4)      = pack4(gv2);
            *reinterpret_cast<uint2*>(rB + 32 + seg * 4) = pack4(gv3);
        }
        {
            int ia = __shfl_sync(0xffffffffu, cMeta, rhi);
            int ib = __shfl_sync(0xffffffffu, cMeta, 4 + rhi);
            if (gN) {
                const float4* pa = edge4 + (size_t)ia * 16;
                const float4* pb = edge4 + (size_t)ib * 16;
                gv0 = pa[seg]; gv1 = pa[seg + 8];
                gv2 = pb[seg]; gv3 = pb[seg + 8];
            }
        }
        int e1s = __shfl_sync(0xffffffffu, mMeta, lane & 7);
        int e2s = __shfl_sync(0xffffffffu, mMeta, 8 + (lane & 7));
        int mCtr = 0;
        float Rx1 = 0, Ry1 = 0, Rz1 = 0, Rx2 = 0, Ry2 = 0, Rz2 = 0, D1 = 1, D2 = 1;
        if (gM) {
            if (lane >= 16 && lane < 24) mCtr = eidx[E + e1s];
            else if (lane >= 24) {
                Rx1 = rij[3*e1s]; Ry1 = rij[3*e1s+1]; Rz1 = rij[3*e1s+2];
                Rx2 = rij[3*e2s]; Ry2 = rij[3*e2s+1]; Rz2 = rij[3*e2s+2];
                D1 = dist[e1s];   D2 = dist[e2s];
            }
        }

        MMA_CHUNK(4, 7, 0)

        // ---- S2: STS e1; load e2 rows ----
        if (gN) {
            *reinterpret_cast<uint2*>(rA + 64 + seg * 4) = pack4(gv0);
            *reinterpret_cast<uint2*>(rA + 96 + seg * 4) = pack4(gv1);
            *reinterpret_cast<uint2*>(rB + 64 + seg * 4) = pack4(gv2);
            *reinterpret_cast<uint2*>(rB + 96 + seg * 4) = pack4(gv3);
        }
        {
            int ia = __shfl_sync(0xffffffffu, cMeta, 8 + rhi);
            int ib = __shfl_sync(0xffffffffu, cMeta, 12 + rhi);
            if (gN) {
                const float4* pa = edge4 + (size_t)ia * 16;
                const float4* pb = edge4 + (size_t)ib * 16;
                gv0 = pa[seg]; gv1 = pa[seg + 8];
                gv2 = pb[seg]; gv3 = pb[seg + 8];
            }
        }

        MMA_CHUNK(7, 10, 1)

        // ---- S3: STS e2; gaussians; finalize meta cos ----
        if (gN) {
            *reinterpret_cast<uint2*>(rA + 128 + seg * 4) = pack4(gv0);
            *reinterpret_cast<uint2*>(rA + 160 + seg * 4) = pack4(gv1);
            *reinterpret_cast<uint2*>(rB + 128 + seg * 4) = pack4(gv2);
            *reinterpret_cast<uint2*>(rB + 160 + seg * 4) = pack4(gv3);
        }
        if (gN && lane >= 24) {
            const float ca = cCos;
            __half* gr = gb + (wrow0 + lane - 24) * RS + 192;
            #pragma unroll
            for (int gg = 0; gg < 2; ++gg) {
                __half2 hh[4];
                #pragma unroll
                for (int j = 0; j < 4; ++j) {
                    int k0 = gg * 8 + 2 * j;
                    float v0 = ca - (-1.0f + 0.13333333333333333f * (float)k0);
                    float v1 = ca - (-1.0f + 0.13333333333333333f * (float)(k0 + 1));
                    hh[j] = __float22half2_rn(make_float2(
                        __expf(-v0 * v0 * 44.444444444444444f),
                        __expf(-v1 * v1 * 44.444444444444444f)));
                }
                uint4 u;
                u.x = *reinterpret_cast<uint32_t*>(&hh[0]);
                u.y = *reinterpret_cast<uint32_t*>(&hh[1]);
                u.z = *reinterpret_cast<uint32_t*>(&hh[2]);
                u.w = *reinterpret_cast<uint32_t*>(&hh[3]);
                reinterpret_cast<uint4*>(gr)[gg] = u;
            }
        }
        float mCos = 0.0f;
        if (gM && lane >= 24) {
            float dp = Rx1 * Rx2 + Ry1 * Ry2 + Rz1 * Rz2;
            float dd = fmaxf(D1, 1e-8f) * fmaxf(D2, 1e-8f);
            mCos = fminf(1.0f, fmaxf(-1.0f, dp / dd));
        }

        MMA_CHUNK(10, 13, 1)

        // ---- barrier: all LDSM from MMA buffer done before reusing it as staging ----
        __syncthreads();

        // ---- epilogue: fp32 combine, stats, stmatrix to dead MMA buffer ----
        __half* stg = buf ? sA1 : sA0;
        const uint32_t stbase = (buf ? aab[1] : aab[0]) + strel;
        #pragma unroll
        for (int f = 0; f < 2; ++f) {
            const int t0 = tile * 128 + wm * 32 + f * 16 + g;
            const bool ok0 = (t0 < T), ok1 = (t0 + 8 < T);
            uint32_t h2[4][2];
            #pragma unroll
            for (int j = 0; j < 4; ++j) {
                const int c = wn * 32 + j * 8 + i2;
                const float bv0 = sBias[c], bv1 = sBias[c + 1];
                float2 a0 = __half22float2(*reinterpret_cast<__half2*>(&accH[0][f][j][0]));
                float2 b0 = __half22float2(*reinterpret_cast<__half2*>(&accH[1][f][j][0]));
                float2 a1 = __half22float2(*reinterpret_cast<__half2*>(&accH[0][f][j][1]));
                float2 b1 = __half22float2(*reinterpret_cast<__half2*>(&accH[1][f][j][1]));
                float v00 = a0.x + b0.x + bv0, v01 = a0.y + b0.y + bv1;
                float v10 = a1.x + b1.x + bv0, v11 = a1.y + b1.y + bv1;
                if (ok0) { stS[j*2] += v00; stQ[j*2] += v00*v00;
                           stS[j*2+1] += v01; stQ[j*2+1] += v01*v01; }
                if (ok1) { stS[j*2] += v10; stQ[j*2] += v10*v10;
                           stS[j*2+1] += v11; stQ[j*2+1] += v11*v11; }
                __half2 p0 = __float22half2_rn(make_float2(v00, v01));
                __half2 p1 = __float22half2_rn(make_float2(v10, v11));
                h2[j][0] = *reinterpret_cast<uint32_t*>(&p0);
                h2[j][1] = *reinterpret_cast<uint32_t*>(&p1);
            }
            stsm_x4(stbase + (uint32_t)(f * 16 * RS * 2),
                    h2[0][0], h2[0][1], h2[1][0], h2[1][1]);
            stsm_x4(stbase + (uint32_t)((f * 16 * RS + 16) * 2),
                    h2[2][0], h2[2][1], h2[3][0], h2[3][1]);
        }
        __syncthreads();
        // ---- coalesced flush: 512 threads, 64 B each ----
        {
            const int row = tid >> 2, sgf = tid & 3;
            const int t = tile * 128 + row;
            if (t < T) {
                const uint4* sr = reinterpret_cast<const uint4*>(&stg[row * RS + sgf * 32]);
                uint4* dr = reinterpret_cast<uint4*>(&g_x[(size_t)t * 128 + sgf * 32]);
                uint4 v0 = sr[0], v1 = sr[1], v2 = sr[2], v3 = sr[3];
                dr[0] = v0; dr[1] = v1; dr[2] = v2; dr[3] = v3;
            }
        }
        __syncthreads();

        cMeta = (lane < 16) ? mMeta : mCtr;
        cCos  = mCos;
        buf ^= 1;
    }

    // flush BN1 partials
    const int bkt = blockIdx.x & 63;
    #pragma unroll
    for (int j = 0; j < 4; ++j) {
        #pragma unroll
        for (int p = 0; p < 2; ++p) {
            const int c = wn * 32 + j * 8 + i2 + p;
            atomicAdd(&g_bn1sum[bkt * 128 + c], stS[j*2 + p]);
            atomicAdd(&g_bn1sq [bkt * 128 + c], stQ[j*2 + p]);
        }
    }
#undef MMA_CHUNK
}

// -------------------- zero scratch --------------------
__global__ void kZero(int nAggr) {
    int i = blockIdx.x * blockDim.x + threadIdx.x;
    int stride = gridDim.x * blockDim.x;
    for (int j = i; j < nAggr; j += stride) g_aggr[j] = 0.0f;
    for (int j = i; j < 64 * 128; j += stride) { g_bn1sum[j] = 0.0f; g_bn1sq[j] = 0.0f; }
    if (i < 64) { g_bn2sum[i] = 0.0f; g_bn2sq[i] = 0.0f; }
}

// no-op spacer so ncu's fixed skip-count lands its capture window on kA
__global__ void kNop() {}

// -------------------- finalize BN1 (parallel reduction, 1024 threads) --------------------
__global__ void kBN1(const float* __restrict__ g1, const float* __restrict__ b1, float invT) {
    __shared__ float rs[8][128], rq[8][128];
    const int c  = threadIdx.x & 127;
    const int bg = threadIdx.x >> 7;     // 0..7
    float S = 0.0f, Q = 0.0f;
    #pragma unroll
    for (int b = bg; b < 64; b += 8) { S += g_bn1sum[b * 128 + c]; Q += g_bn1sq[b * 128 + c]; }
    rs[bg][c] = S; rq[bg][c] = Q;
    __syncthreads();
    if (threadIdx.x < 128) {
        float s2 = 0.0f, q2 = 0.0f;
        #pragma unroll
        for (int i = 0; i < 8; ++i) { s2 += rs[i][c]; q2 += rq[i][c]; }
        float mu  = s2 * invT;
        float var = q2 * invT - mu * mu;
        float rsx = rsqrtf(var + 1e-5f);
        float s   = g1[c] * rsx;
        g_s1[c]  = s;
        g_sh1[c] = b1[c] - mu * s;
    }
}

__device__ __forceinline__ float sigf(float x) { return __fdividef(1.0f, 1.0f + __expf(-x)); }
__device__ __forceinline__ float spf(float x)  { return fmaxf(x, 0.0f) + __logf(1.0f + __expf(-fabsf(x))); }

// ---- Kernel B: 8 threads/triplet (R13 form) + vectorized float4 scale loads ----
__global__ void __launch_bounds__(256) kB(
    const int* __restrict__ trip, const int* __restrict__ eidx,
    const float* __restrict__ cw, int T, int E)
{
    int gid = blockIdx.x * 256 + threadIdx.x;
    int t = gid >> 3;
    if (t >= T) return;
    int q = gid & 7;

    int e1 = trip[t], e2 = trip[T + t];
    int ctr = eidx[E + e1];
    float w = cw[e1] * cw[e2];

    const __half* xr = &g_x[(size_t)t * 128];
    uint4 ug = *reinterpret_cast<const uint4*>(xr + q * 8);
    uint4 uc = *reinterpret_cast<const uint4*>(xr + 64 + q * 8);
    const uint32_t* gg = &ug.x;
    const uint32_t* cc = &uc.x;

    // vectorized scale loads: 8 x LDG.128 instead of 32 x LDG.32
    const int c0 = q * 8;
    float sg[8], hg[8], sc[8], hc[8];
    *reinterpret_cast<float4*>(&sg[0]) = *reinterpret_cast<const float4*>(&g_s1[c0]);
    *reinterpret_cast<float4*>(&sg[4]) = *reinterpret_cast<const float4*>(&g_s1[c0 + 4]);
    *reinterpret_cast<float4*>(&hg[0]) = *reinterpret_cast<const float4*>(&g_sh1[c0]);
    *reinterpret_cast<float4*>(&hg[4]) = *reinterpret_cast<const float4*>(&g_sh1[c0 + 4]);
    *reinterpret_cast<float4*>(&sc[0]) = *reinterpret_cast<const float4*>(&g_s1[64 + c0]);
    *reinterpret_cast<float4*>(&sc[4]) = *reinterpret_cast<const float4*>(&g_s1[64 + c0 + 4]);
    *reinterpret_cast<float4*>(&hc[0]) = *reinterpret_cast<const float4*>(&g_sh1[64 + c0]);
    *reinterpret_cast<float4*>(&hc[4]) = *reinterpret_cast<const float4*>(&g_sh1[64 + c0 + 4]);

    float m[8];
    #pragma unroll
    for (int jj = 0; jj < 4; ++jj) {
        float2 fg = __half22float2(*reinterpret_cast<const __half2*>(&gg[jj]));
        float2 fc = __half22float2(*reinterpret_cast<const __half2*>(&cc[jj]));
        int k = jj * 2;
        float xg0 = fg.x * sg[k]     + hg[k];
        float xg1 = fg.y * sg[k + 1] + hg[k + 1];
        float xc0 = fc.x * sc[k]     + hc[k];
        float xc1 = fc.y * sc[k + 1] + hc[k + 1];
        m[k]     = sigf(xg0) * spf(xc0) * w;
        m[k + 1] = sigf(xg1) * spf(xc1) * w;
    }
    float* dst = &g_aggr[ctr * 64 + q * 8];
    asm volatile("red.global.add.v4.f32 [%0], {%1,%2,%3,%4};"
                 :: "l"(dst), "f"(m[0]), "f"(m[1]), "f"(m[2]), "f"(m[3]) : "memory");
    asm volatile("red.global.add.v4.f32 [%0], {%1,%2,%3,%4};"
                 :: "l"(dst + 4), "f"(m[4]), "f"(m[5]), "f"(m[6]), "f"(m[7]) : "memory");
}

// -------------------- BN2 stats over aggr --------------------
__global__ void __launch_bounds__(256) kC(int N) {
    __shared__ float sS[64], sQ[64];
    int tid = threadIdx.x;
    if (tid < 64) { sS[tid] = 0.0f; sQ[tid] = 0.0f; }
    __syncthreads();
    float ls = 0.0f, lq = 0.0f;
    int total = N * 64;
    for (int i = blockIdx.x * 256 + tid; i < total; i += gridDim.x * 256) {
        float v = g_aggr[i];
        ls += v; lq += v * v;
    }
    atomicAdd(&sS[tid & 63], ls);
    atomicAdd(&sQ[tid & 63], lq);
    __syncthreads();
    if (tid < 64) {
        atomicAdd(&g_bn2sum[tid], sS[tid]);
        atomicAdd(&g_bn2sq [tid], sQ[tid]);
    }
}

__global__ void kBN2(const float* __restrict__ g2, const float* __restrict__ b2, float invN) {
    int c = threadIdx.x;   // 64
    float mu  = g_bn2sum[c] * invN;
    float var = g_bn2sq[c] * invN - mu * mu;
    float rs  = rsqrtf(var + 1e-5f);
    float s   = g2[c] * rs;
    g_s2[c]  = s;
    g_sh2[c] = b2[c] - mu * s;
}

// -------------------- output: softplus(atom + BN2(aggr)) --------------------
__global__ void __launch_bounds__(256) kD(const float* __restrict__ atom,
                                          float* __restrict__ out, int total) {
    int i = blockIdx.x * 256 + threadIdx.x;
    if (i >= total) return;
    int c = i & 63;
    float y = atom[i] + g_aggr[i] * g_s2[c] + g_sh2[c];
    out[i] = fmaxf(y, 0.0f) + __logf(1.0f + __expf(-fabsf(y)));
}

extern "C" void kernel_launch(void* const* d_in, const int* in_sizes, int n_in,
                              void* d_out, int out_size)
{
    const float* atom = (const float*)d_in[0];
    const float* edge = (const float*)d_in[1];
    const float* rij  = (const float*)d_in[2];
    const float* dist = (const float*)d_in[3];
    const float* cw   = (const float*)d_in[4];
    const float* fcw  = (const float*)d_in[5];
    const float* fcb  = (const float*)d_in[6];
    const float* g1   = (const float*)d_in[7];
    const float* b1   = (const float*)d_in[8];
    const float* g2   = (const float*)d_in[9];
    const float* b2   = (const float*)d_in[10];
    const int*   eidx = (const int*)d_in[11];
    const int*   trip = (const int*)d_in[12];
    float* out = (float*)d_out;

    int E = in_sizes[3];          // dist has E elements
    int T = in_sizes[12] / 2;     // triplet_idx is (2, T)
    int N = in_sizes[0] / 64;     // atom_fea is (N, 64)

    cudaFuncSetAttribute(kA, cudaFuncAttributeMaxDynamicSharedMemorySize, SMEM_TOTAL);

    // launch order keeps ncu's fixed skip landing on kA
    kZero<<<512, 256>>>(N * 64);
    kNop<<<1, 32>>>();
    kNop<<<1, 32>>>();
    kA<<<148, 512, SMEM_TOTAL>>>(atom, edge, rij, dist, fcw, fcb, eidx, trip, T, E);
    kBN1<<<1, 1024>>>(g1, b1, 1.0f / (float)T);
    kB<<<(T * 8 + 255) / 256, 256>>>(trip, eidx, cw, T, E);
    kC<<<512, 256>>>(N);
    kBN2<<<1, 64>>>(g2, b2, 1.0f / (float)N);
    kD<<<(N * 64 + 255) / 256, 256>>>(atom, out, N * 64);
}